// round 1
// baseline (speedup 1.0000x reference)
#include <cuda_runtime.h>
#include <cuda_bf16.h>
#include <math.h>

// ---------------- problem constants ----------------
#define BATCH   16384
#define N_IN    128
#define CTX     128
#define HDIM    1024
#define NB      8
#define OUT_MULT 23              // 3*NB - 1
#define N_OUT   (N_IN * OUT_MULT)   // 2944
#define KCAT    (CTX + N_IN)        // 256
#define TAIL    3.0f
#define MIN_W   0.001f
#define MIN_H   0.001f
#define MIN_D   0.001f
#define RQS_SCALE 724.07734393502f  // sqrt(1024*1024/2)

// ---------------- scratch (static device globals; no allocation) ----------------
__device__ float g_xcat[(size_t)BATCH * KCAT];     // [B,256] = [context | x]
__device__ float g_wcat[(size_t)HDIM * KCAT];      // [1024,256] = [ctx_w | w0*m0]
__device__ float g_w1m [(size_t)HDIM * HDIM];      // w1 * m1
__device__ float g_w2m [(size_t)N_OUT * HDIM];     // w2 * m2
__device__ float g_h0  [(size_t)BATCH * HDIM];
__device__ float g_h1  [(size_t)BATCH * HDIM];
__device__ float g_out [(size_t)BATCH * N_OUT];

// ---------------- prep kernels (masks recomputed analytically) ----------------
// deg_in[i]  = i+1
// deg_h[h]   = h % 127 + 1
// deg_out[o] = o/23 + 1
// m0[h,i] = deg_h >= deg_in  <=>  (h%127) >= i
// m1[h,h2] = (h%127) >= (h2%127)
// m2[o,h] = deg_out > deg_h  <=>  (o/23) > (h%127)

__global__ void k_prep_xcat(const float* __restrict__ x, const float* __restrict__ ctx,
                            float* __restrict__ xcat) {
    int idx = blockIdx.x * blockDim.x + threadIdx.x;
    if (idx >= BATCH * KCAT) return;
    int b = idx >> 8, c = idx & 255;
    xcat[idx] = (c < CTX) ? ctx[b * CTX + c] : x[b * N_IN + (c - CTX)];
}

__global__ void k_prep_wcat(const float* __restrict__ ctxw, const float* __restrict__ w0,
                            float* __restrict__ wcat) {
    int idx = blockIdx.x * blockDim.x + threadIdx.x;
    if (idx >= HDIM * KCAT) return;
    int h = idx >> 8, c = idx & 255;
    if (c < CTX) {
        wcat[idx] = ctxw[h * CTX + c];
    } else {
        int i = c - CTX;
        wcat[idx] = ((h % 127) >= i) ? w0[h * N_IN + i] : 0.0f;
    }
}

__global__ void k_prep_w1(const float* __restrict__ w1, float* __restrict__ w1m) {
    int idx = blockIdx.x * blockDim.x + threadIdx.x;
    if (idx >= HDIM * HDIM) return;
    int h = idx >> 10, h2 = idx & 1023;
    w1m[idx] = ((h % 127) >= (h2 % 127)) ? w1[idx] : 0.0f;
}

__global__ void k_prep_w2(const float* __restrict__ w2, float* __restrict__ w2m) {
    int idx = blockIdx.x * blockDim.x + threadIdx.x;
    if (idx >= N_OUT * HDIM) return;
    int o = idx >> 10, h = idx & 1023;
    w2m[idx] = ((o / OUT_MULT) > (h % 127)) ? w2[idx] : 0.0f;
}

// ---------------- SGEMM: C[M,N] = A[M,K] @ B[N,K]^T + bias, optional relu --------
// Classic 128x128 block tile, BK=8, 256 threads, 8x8 per-thread microtile.
// Requires: M%128==0, N%128==0, K%8==0 (true for all three layers).
__global__ __launch_bounds__(256, 2)
void sgemm_tn(const float* __restrict__ A, const float* __restrict__ B,
              const float* __restrict__ bias, float* __restrict__ C,
              int M, int N, int K, int relu) {
    __shared__ float As[8][128];
    __shared__ float Bs[8][128];

    const int tid = threadIdx.x;
    const int tx = tid & 15;          // 0..15 -> N microtile
    const int ty = tid >> 4;          // 0..15 -> M microtile
    const int bm = blockIdx.y * 128;
    const int bn = blockIdx.x * 128;

    const int lrow = tid >> 1;        // 0..127
    const int lcol = (tid & 1) * 4;   // 0 or 4

    const float* Ab = A + (size_t)(bm + lrow) * K + lcol;
    const float* Bb = B + (size_t)(bn + lrow) * K + lcol;

    float acc[8][8];
#pragma unroll
    for (int i = 0; i < 8; i++)
#pragma unroll
        for (int j = 0; j < 8; j++) acc[i][j] = 0.0f;

    for (int k0 = 0; k0 < K; k0 += 8) {
        float4 a4 = *(const float4*)(Ab + k0);
        float4 b4 = *(const float4*)(Bb + k0);
        As[lcol + 0][lrow] = a4.x; As[lcol + 1][lrow] = a4.y;
        As[lcol + 2][lrow] = a4.z; As[lcol + 3][lrow] = a4.w;
        Bs[lcol + 0][lrow] = b4.x; Bs[lcol + 1][lrow] = b4.y;
        Bs[lcol + 2][lrow] = b4.z; Bs[lcol + 3][lrow] = b4.w;
        __syncthreads();

#pragma unroll
        for (int k = 0; k < 8; k++) {
            float4 am0 = *(const float4*)&As[k][ty * 8];
            float4 am1 = *(const float4*)&As[k][ty * 8 + 4];
            float4 bn0 = *(const float4*)&Bs[k][tx * 8];
            float4 bn1 = *(const float4*)&Bs[k][tx * 8 + 4];
            float ar[8] = {am0.x, am0.y, am0.z, am0.w, am1.x, am1.y, am1.z, am1.w};
            float br[8] = {bn0.x, bn0.y, bn0.z, bn0.w, bn1.x, bn1.y, bn1.z, bn1.w};
#pragma unroll
            for (int i = 0; i < 8; i++)
#pragma unroll
                for (int j = 0; j < 8; j++)
                    acc[i][j] = fmaf(ar[i], br[j], acc[i][j]);
        }
        __syncthreads();
    }

    // epilogue: bias + optional relu
#pragma unroll
    for (int i = 0; i < 8; i++) {
        int row = bm + ty * 8 + i;
        float* crow = C + (size_t)row * N + bn + tx * 8;
#pragma unroll
        for (int j = 0; j < 8; j++) {
            float v = acc[i][j] + bias[bn + tx * 8 + j];
            if (relu) v = fmaxf(v, 0.0f);
            crow[j] = v;
        }
    }
}

// ---------------- RQS spline + logdet reduction ----------------
__device__ __forceinline__ float softplusf(float v) {
    return (v > 20.0f) ? v : log1pf(expf(v));
}

__global__ void k_spline(const float* __restrict__ x, const float* __restrict__ out,
                         float* __restrict__ y_out, float* __restrict__ ld_out) {
    const int b = blockIdx.x;       // batch row
    const int i = threadIdx.x;      // feature 0..127

    const float* o = out + ((size_t)b * N_IN + i) * OUT_MULT;
    const float xi = x[(size_t)b * N_IN + i];

    // softmax(uw), softmax(uh)
    float uw[NB], uh[NB];
#pragma unroll
    for (int j = 0; j < NB; j++) {
        uw[j] = o[j]      * (1.0f / RQS_SCALE);
        uh[j] = o[NB + j] * (1.0f / RQS_SCALE);
    }
    float mw = uw[0], mh = uh[0];
#pragma unroll
    for (int j = 1; j < NB; j++) { mw = fmaxf(mw, uw[j]); mh = fmaxf(mh, uh[j]); }
    float ew[NB], eh[NB], sw = 0.0f, sh = 0.0f;
#pragma unroll
    for (int j = 0; j < NB; j++) {
        ew[j] = expf(uw[j] - mw); sw += ew[j];
        eh[j] = expf(uh[j] - mh); sh += eh[j];
    }
    const float rw = (1.0f - MIN_W * NB) / sw;
    const float rh = (1.0f - MIN_H * NB) / sh;

    // knot positions
    float cw[NB + 1], ch[NB + 1];
    cw[0] = -TAIL; ch[0] = -TAIL;
    float accw = 0.0f, acch = 0.0f;
#pragma unroll
    for (int j = 0; j < NB; j++) {
        accw += MIN_W + rw * ew[j];
        acch += MIN_H + rh * eh[j];
        cw[j + 1] = 2.0f * TAIL * accw - TAIL;
        ch[j + 1] = 2.0f * TAIL * acch - TAIL;
    }
    cw[NB] = TAIL; ch[NB] = TAIL;

    // derivatives (pad gives exactly MIN_D + softplus(DPAD) = 1.0)
    float d[NB + 1];
    d[0] = 1.0f; d[NB] = 1.0f;
#pragma unroll
    for (int j = 1; j < NB; j++) d[j] = MIN_D + softplusf(o[2 * NB + j - 1]);

    const float xc = fminf(fmaxf(xi, -TAIL), TAIL);

    int idx = 0;
#pragma unroll
    for (int k = 1; k <= NB; k++) idx += (xc >= cw[k]) ? 1 : 0;
    idx = min(idx, NB - 1);

    const float in_cw = cw[idx];
    const float in_w  = cw[idx + 1] - cw[idx];
    const float in_ch = ch[idx];
    const float in_h  = ch[idx + 1] - ch[idx];
    const float delta = in_h / in_w;
    const float d0 = d[idx], d1 = d[idx + 1];

    const float theta = (xc - in_cw) / in_w;
    const float t1m   = theta * (1.0f - theta);
    const float denom = delta + (d0 + d1 - 2.0f * delta) * t1m;
    const float num   = in_h * (delta * theta * theta + d0 * t1m);
    float y  = in_ch + num / denom;
    float ld = 2.0f * logf(delta)
             + logf(d1 * theta * theta + 2.0f * delta * t1m + d0 * (1.0f - theta) * (1.0f - theta))
             - 2.0f * logf(denom);

    const bool inside = fabsf(xi) <= TAIL;
    y_out[(size_t)b * N_IN + i] = inside ? y : xi;
    float ldv = inside ? ld : 0.0f;

    // block reduction of logdet over 128 threads
    __shared__ float warp_sums[4];
#pragma unroll
    for (int off = 16; off > 0; off >>= 1)
        ldv += __shfl_down_sync(0xFFFFFFFFu, ldv, off);
    if ((i & 31) == 0) warp_sums[i >> 5] = ldv;
    __syncthreads();
    if (i == 0)
        ld_out[b] = warp_sums[0] + warp_sums[1] + warp_sums[2] + warp_sums[3];
}

// ---------------- launch ----------------
extern "C" void kernel_launch(void* const* d_in, const int* in_sizes, int n_in,
                              void* d_out, int out_size) {
    const float* x      = (const float*)d_in[0];
    const float* context= (const float*)d_in[1];
    const float* ctx_w  = (const float*)d_in[2];
    const float* w0     = (const float*)d_in[3];
    const float* b0     = (const float*)d_in[4];
    const float* w1     = (const float*)d_in[5];
    const float* b1     = (const float*)d_in[6];
    const float* w2     = (const float*)d_in[7];
    const float* b2     = (const float*)d_in[8];
    // masks d_in[9..11] ignored: recomputed analytically in-kernel.

    float *xcat, *wcat, *w1m, *w2m, *h0, *h1, *obuf;
    cudaGetSymbolAddress((void**)&xcat, g_xcat);
    cudaGetSymbolAddress((void**)&wcat, g_wcat);
    cudaGetSymbolAddress((void**)&w1m,  g_w1m);
    cudaGetSymbolAddress((void**)&w2m,  g_w2m);
    cudaGetSymbolAddress((void**)&h0,   g_h0);
    cudaGetSymbolAddress((void**)&h1,   g_h1);
    cudaGetSymbolAddress((void**)&obuf, g_out);

    const int TPB = 256;
    k_prep_xcat<<<(BATCH * KCAT + TPB - 1) / TPB, TPB>>>(x, context, xcat);
    k_prep_wcat<<<(HDIM * KCAT + TPB - 1) / TPB, TPB>>>(ctx_w, w0, wcat);
    k_prep_w1 <<<(HDIM * HDIM + TPB - 1) / TPB, TPB>>>(w1, w1m);
    k_prep_w2 <<<(N_OUT * HDIM + TPB - 1) / TPB, TPB>>>(w2, w2m);

    // layer 1: [B,256] @ [1024,256]^T -> h0 (relu)
    sgemm_tn<<<dim3(HDIM / 128, BATCH / 128), 256>>>(xcat, wcat, b0, h0, BATCH, HDIM, KCAT, 1);
    // layer 2: [B,1024] @ [1024,1024]^T -> h1 (relu)
    sgemm_tn<<<dim3(HDIM / 128, BATCH / 128), 256>>>(h0, w1m, b1, h1, BATCH, HDIM, HDIM, 1);
    // layer 3: [B,1024] @ [2944,1024]^T -> out (no relu)
    sgemm_tn<<<dim3(N_OUT / 128, BATCH / 128), 256>>>(h1, w2m, b2, obuf, BATCH, N_OUT, HDIM, 0);

    // spline + logdet; output = [y (B*128 floats) | logdet (B floats)]
    float* yout = (float*)d_out;
    float* ldout = (float*)d_out + (size_t)BATCH * N_IN;
    k_spline<<<BATCH, N_IN>>>(x, obuf, yout, ldout);
}

// round 3
// speedup vs baseline: 3.0592x; 3.0592x over previous
#include <cuda_runtime.h>
#include <cuda_bf16.h>
#include <math.h>
#include <stdint.h>

// ---------------- problem constants ----------------
#define BATCH   16384
#define N_IN    128
#define CTX     128
#define HDIM    1024
#define NB      8
#define OUT_MULT 23                  // 3*NB - 1
#define N_OUT   (N_IN * OUT_MULT)    // 2944
#define N_OUT_P 3072                 // padded
#define KCAT    (CTX + N_IN)         // 256
#define TAIL    3.0f
#define MIN_W   0.001f
#define MIN_H   0.001f
#define MIN_D   0.001f
#define RQS_SCALE 724.07734393502f   // sqrt(1024*1024/2)

// ---------------- scratch ----------------
__device__ __nv_bfloat16 g_xcat_hi[(size_t)BATCH * KCAT];
__device__ __nv_bfloat16 g_xcat_lo[(size_t)BATCH * KCAT];
__device__ __nv_bfloat16 g_wcat_hi[(size_t)HDIM * KCAT];
__device__ __nv_bfloat16 g_wcat_lo[(size_t)HDIM * KCAT];
__device__ __nv_bfloat16 g_w1_hi[(size_t)HDIM * HDIM];
__device__ __nv_bfloat16 g_w1_lo[(size_t)HDIM * HDIM];
__device__ __nv_bfloat16 g_w2_hi[(size_t)N_OUT_P * HDIM];
__device__ __nv_bfloat16 g_w2_lo[(size_t)N_OUT_P * HDIM];
__device__ __nv_bfloat16 g_h0_hi[(size_t)BATCH * HDIM];
__device__ __nv_bfloat16 g_h0_lo[(size_t)BATCH * HDIM];
__device__ __nv_bfloat16 g_h1_hi[(size_t)BATCH * HDIM];
__device__ __nv_bfloat16 g_h1_lo[(size_t)BATCH * HDIM];
__device__ float         g_out[(size_t)BATCH * N_OUT_P];

// ---------------- baseline-PTX helpers (NO tcgen05 — compute_103 safe) ------
__device__ __forceinline__ uint32_t smem_to_u32(const void* p) {
    uint32_t a;
    asm("{ .reg .u64 t; cvta.to.shared.u64 t, %1; cvt.u32.u64 %0, t; }" : "=r"(a) : "l"(p));
    return a;
}

#define CP_ASYNC16(saddr, gptr) \
    asm volatile("cp.async.cg.shared.global [%0], [%1], 16;" :: "r"(saddr), "l"(gptr) : "memory")
#define CP_COMMIT()   asm volatile("cp.async.commit_group;" ::: "memory")
#define CP_WAIT(n)    asm volatile("cp.async.wait_group %0;" :: "n"(n) : "memory")

#define LDSM4(R, addr) \
    asm volatile("ldmatrix.sync.aligned.m8n8.x4.shared.b16 {%0,%1,%2,%3}, [%4];" \
        : "=r"((R)[0]), "=r"((R)[1]), "=r"((R)[2]), "=r"((R)[3]) : "r"(addr))
#define LDSM2(R, addr) \
    asm volatile("ldmatrix.sync.aligned.m8n8.x2.shared.b16 {%0,%1}, [%2];" \
        : "=r"((R)[0]), "=r"((R)[1]) : "r"(addr))

#define MMA_BF16(C, A, B) \
    asm volatile("mma.sync.aligned.m16n8k16.row.col.f32.bf16.bf16.f32 " \
        "{%0,%1,%2,%3}, {%4,%5,%6,%7}, {%8,%9}, {%0,%1,%2,%3};" \
        : "+f"((C)[0]), "+f"((C)[1]), "+f"((C)[2]), "+f"((C)[3]) \
        : "r"((A)[0]), "r"((A)[1]), "r"((A)[2]), "r"((A)[3]), "r"((B)[0]), "r"((B)[1]))

// ---------------- prep kernels (masks analytic, bf16 split) ----------------
__device__ __forceinline__ void split_bf16(float v, __nv_bfloat16& h, __nv_bfloat16& l) {
    h = __float2bfloat16_rn(v);
    l = __float2bfloat16_rn(v - __bfloat162float(h));
}

__global__ void k_prep_xcat(const float* __restrict__ x, const float* __restrict__ ctx,
                            __nv_bfloat16* __restrict__ hi, __nv_bfloat16* __restrict__ lo) {
    int idx = blockIdx.x * blockDim.x + threadIdx.x;
    if (idx >= BATCH * KCAT) return;
    int b = idx >> 8, c = idx & 255;
    float v = (c < CTX) ? ctx[b * CTX + c] : x[b * N_IN + (c - CTX)];
    split_bf16(v, hi[idx], lo[idx]);
}

__global__ void k_prep_wcat(const float* __restrict__ ctxw, const float* __restrict__ w0,
                            __nv_bfloat16* __restrict__ hi, __nv_bfloat16* __restrict__ lo) {
    int idx = blockIdx.x * blockDim.x + threadIdx.x;
    if (idx >= HDIM * KCAT) return;
    int h = idx >> 8, c = idx & 255;
    float v;
    if (c < CTX) v = ctxw[h * CTX + c];
    else { int i = c - CTX; v = ((h % 127) >= i) ? w0[h * N_IN + i] : 0.0f; }
    split_bf16(v, hi[idx], lo[idx]);
}

__global__ void k_prep_w1(const float* __restrict__ w1,
                          __nv_bfloat16* __restrict__ hi, __nv_bfloat16* __restrict__ lo) {
    int idx = blockIdx.x * blockDim.x + threadIdx.x;
    if (idx >= HDIM * HDIM) return;
    int h = idx >> 10, h2 = idx & 1023;
    float v = ((h % 127) >= (h2 % 127)) ? w1[idx] : 0.0f;
    split_bf16(v, hi[idx], lo[idx]);
}

__global__ void k_prep_w2(const float* __restrict__ w2,
                          __nv_bfloat16* __restrict__ hi, __nv_bfloat16* __restrict__ lo) {
    int idx = blockIdx.x * blockDim.x + threadIdx.x;
    if (idx >= N_OUT_P * HDIM) return;
    int o = idx >> 10, h = idx & 1023;
    float v = 0.0f;
    if (o < N_OUT && ((o / OUT_MULT) > (h % 127))) v = w2[(size_t)o * HDIM + h];
    split_bf16(v, hi[idx], lo[idx]);
}

// ---------------- mma.sync split-bf16 GEMM ----------------
// C[M,N] = A[M,K] @ B[N,K]^T, A=Ahi+Alo, B=Bhi+Blo (drop lo*lo).
// CTA tile 128x128, BK=64 (128B rows), 8 warps as 4(M) x 2(N), warp tile 32x64.
// SMEM stage 64KB: Ahi|Alo|Bhi|Blo each 16KB, double buffered.
// XOR swizzle: 16B chunk c at row r stored at chunk (c ^ (r&7)).

#define ST_AHI 0
#define ST_ALO 16384
#define ST_BHI 32768
#define ST_BLO 49152
#define STAGE_SZ 65536
#define GSMEM (2 * STAGE_SZ + 1024)

__global__ __launch_bounds__(256, 1)
void gemm_mma(const __nv_bfloat16* __restrict__ Ahi, const __nv_bfloat16* __restrict__ Alo,
              const __nv_bfloat16* __restrict__ Bhi, const __nv_bfloat16* __restrict__ Blo,
              const float* __restrict__ bias, int K, int nvalid,
              __nv_bfloat16* __restrict__ Chi, __nv_bfloat16* __restrict__ Clo,
              float* __restrict__ Cf, int ldc) {
    extern __shared__ char smem[];
    const uint32_t sb = smem_to_u32(smem);
    float* bias_s = (float*)(smem + 2 * STAGE_SZ);

    const int tid = threadIdx.x;
    const int lane = tid & 31, wid = tid >> 5;
    const int gm = blockIdx.y * 128;
    const int gn = blockIdx.x * 128;

    if (tid < 128) bias_s[tid] = (gn + tid < nvalid) ? bias[gn + tid] : 0.0f;

    // cp.async source/dest precompute: thread covers 4 (row,chunk) units per matrix
    int r_[4], c_[4]; uint32_t soff_[4];
#pragma unroll
    for (int i = 0; i < 4; i++) {
        int u = i * 256 + tid;
        r_[i] = u >> 3; c_[i] = u & 7;
        soff_[i] = (uint32_t)(r_[i] * 128 + ((c_[i] ^ (r_[i] & 7)) << 4));
    }

    // ldmatrix per-lane bases
    const int wm = (wid & 3) * 32;          // warp M origin (within tile)
    const int nb = (wid >> 2) * 64;         // warp N origin
    const int lr = lane & 7;
    const int gA = (lane >> 3) & 1;         // row-half selector for A
    const int cpartA = (lane >> 4) & 1;     // k-chunk selector for A
    const int cpartB = (lane >> 3) & 1;     // k-chunk selector for B
    const uint32_t xorv = (uint32_t)lr << 4;
    const uint32_t pA = (uint32_t)((wm + gA * 8 + lr) * 128);
    const uint32_t pB = (uint32_t)((nb + lr) * 128);

    float acc[2][8][4];
#pragma unroll
    for (int t = 0; t < 2; t++)
#pragma unroll
        for (int j = 0; j < 8; j++)
#pragma unroll
            for (int q = 0; q < 4; q++) acc[t][j][q] = 0.0f;

    const int nch = K >> 6;

    // stage loader
    auto load_stage = [&](int s, int k0) {
        uint32_t base = sb + (uint32_t)s * STAGE_SZ;
#pragma unroll
        for (int i = 0; i < 4; i++) {
            size_t ga = (size_t)(gm + r_[i]) * K + k0 + c_[i] * 8;
            size_t gb = (size_t)(gn + r_[i]) * K + k0 + c_[i] * 8;
            CP_ASYNC16(base + ST_AHI + soff_[i], Ahi + ga);
            CP_ASYNC16(base + ST_ALO + soff_[i], Alo + ga);
            CP_ASYNC16(base + ST_BHI + soff_[i], Bhi + gb);
            CP_ASYNC16(base + ST_BLO + soff_[i], Blo + gb);
        }
    };

    load_stage(0, 0);
    CP_COMMIT();

    for (int c = 0; c < nch; c++) {
        if (c + 1 < nch) { load_stage((c + 1) & 1, (c + 1) << 6); CP_COMMIT(); }
        if (c + 1 < nch) CP_WAIT(1); else CP_WAIT(0);
        __syncthreads();

        const uint32_t sA = sb + (uint32_t)(c & 1) * STAGE_SZ;
#pragma unroll
        for (int ks = 0; ks < 4; ks++) {
            const uint32_t offA = (uint32_t)(((ks * 2 + cpartA) << 4)) ^ xorv;
            const uint32_t offB = (uint32_t)(((ks * 2 + cpartB) << 4)) ^ xorv;
            uint32_t ah0[4], ah1[4], al0[4], al1[4];
            LDSM4(ah0, sA + ST_AHI + pA + offA);
            LDSM4(ah1, sA + ST_AHI + pA + 2048 + offA);
            LDSM4(al0, sA + ST_ALO + pA + offA);
            LDSM4(al1, sA + ST_ALO + pA + 2048 + offA);
#pragma unroll
            for (int j = 0; j < 8; j++) {
                uint32_t bh[2], bl[2];
                LDSM2(bh, sA + ST_BHI + pB + (uint32_t)(j * 1024) + offB);
                LDSM2(bl, sA + ST_BLO + pB + (uint32_t)(j * 1024) + offB);
                MMA_BF16(acc[0][j], ah0, bh);
                MMA_BF16(acc[1][j], ah1, bh);
                MMA_BF16(acc[0][j], ah0, bl);
                MMA_BF16(acc[1][j], ah1, bl);
                MMA_BF16(acc[0][j], al0, bh);
                MMA_BF16(acc[1][j], al1, bh);
            }
        }
        __syncthreads();
    }

    // ---------------- epilogue ----------------
    const int qrow = lane >> 2;             // 0..7
    const int qcol = 2 * (lane & 3);        // 0,2,4,6
#pragma unroll
    for (int t = 0; t < 2; t++) {
#pragma unroll
        for (int j = 0; j < 8; j++) {
            const int colL = nb + j * 8 + qcol;
            const float b0 = bias_s[colL], b1 = bias_s[colL + 1];
#pragma unroll
            for (int h = 0; h < 2; h++) {   // row halves (+0 / +8)
                const int row = gm + wm + t * 16 + h * 8 + qrow;
                float v0 = acc[t][j][h * 2 + 0] + b0;
                float v1 = acc[t][j][h * 2 + 1] + b1;
                if (Cf) {
                    float2 f2 = make_float2(v0, v1);
                    *(float2*)(Cf + (size_t)row * ldc + gn + colL) = f2;
                } else {
                    v0 = fmaxf(v0, 0.0f); v1 = fmaxf(v1, 0.0f);
                    __nv_bfloat16 h0 = __float2bfloat16_rn(v0);
                    __nv_bfloat16 h1 = __float2bfloat16_rn(v1);
                    __nv_bfloat16 l0 = __float2bfloat16_rn(v0 - __bfloat162float(h0));
                    __nv_bfloat16 l1 = __float2bfloat16_rn(v1 - __bfloat162float(h1));
                    uint32_t wh = (uint32_t)__bfloat16_as_ushort(h0) | ((uint32_t)__bfloat16_as_ushort(h1) << 16);
                    uint32_t wl = (uint32_t)__bfloat16_as_ushort(l0) | ((uint32_t)__bfloat16_as_ushort(l1) << 16);
                    *(uint32_t*)(Chi + (size_t)row * ldc + gn + colL) = wh;
                    *(uint32_t*)(Clo + (size_t)row * ldc + gn + colL) = wl;
                }
            }
        }
    }
}

// ---------------- RQS spline + logdet reduction ----------------
__device__ __forceinline__ float softplusf(float v) {
    return (v > 20.0f) ? v : log1pf(expf(v));
}

__global__ void k_spline(const float* __restrict__ x, const float* __restrict__ out,
                         float* __restrict__ y_out, float* __restrict__ ld_out) {
    const int b = blockIdx.x;
    const int i = threadIdx.x;

    __shared__ float srow[N_OUT];
    const float4* orow = (const float4*)(out + (size_t)b * N_OUT_P);
#pragma unroll
    for (int u = i; u < N_OUT / 4; u += N_IN) ((float4*)srow)[u] = orow[u];
    __syncthreads();

    const float* o = srow + i * OUT_MULT;
    const float xi = x[(size_t)b * N_IN + i];

    float uw[NB], uh[NB];
#pragma unroll
    for (int j = 0; j < NB; j++) {
        uw[j] = o[j]      * (1.0f / RQS_SCALE);
        uh[j] = o[NB + j] * (1.0f / RQS_SCALE);
    }
    float mw = uw[0], mh = uh[0];
#pragma unroll
    for (int j = 1; j < NB; j++) { mw = fmaxf(mw, uw[j]); mh = fmaxf(mh, uh[j]); }
    float ew[NB], eh[NB], sw = 0.0f, sh = 0.0f;
#pragma unroll
    for (int j = 0; j < NB; j++) {
        ew[j] = expf(uw[j] - mw); sw += ew[j];
        eh[j] = expf(uh[j] - mh); sh += eh[j];
    }
    const float rw = (1.0f - MIN_W * NB) / sw;
    const float rh = (1.0f - MIN_H * NB) / sh;

    float cw[NB + 1], ch[NB + 1];
    cw[0] = -TAIL; ch[0] = -TAIL;
    float accw = 0.0f, acch = 0.0f;
#pragma unroll
    for (int j = 0; j < NB; j++) {
        accw += MIN_W + rw * ew[j];
        acch += MIN_H + rh * eh[j];
        cw[j + 1] = 2.0f * TAIL * accw - TAIL;
        ch[j + 1] = 2.0f * TAIL * acch - TAIL;
    }
    cw[NB] = TAIL; ch[NB] = TAIL;

    float d[NB + 1];
    d[0] = 1.0f; d[NB] = 1.0f;
#pragma unroll
    for (int j = 1; j < NB; j++) d[j] = MIN_D + softplusf(o[2 * NB + j - 1]);

    const float xc = fminf(fmaxf(xi, -TAIL), TAIL);
    int idx = 0;
#pragma unroll
    for (int k = 1; k <= NB; k++) idx += (xc >= cw[k]) ? 1 : 0;
    idx = min(idx, NB - 1);

    const float in_cw = cw[idx];
    const float in_w  = cw[idx + 1] - cw[idx];
    const float in_ch = ch[idx];
    const float in_h  = ch[idx + 1] - ch[idx];
    const float delta = in_h / in_w;
    const float d0 = d[idx], d1 = d[idx + 1];

    const float theta = (xc - in_cw) / in_w;
    const float t1m   = theta * (1.0f - theta);
    const float denom = delta + (d0 + d1 - 2.0f * delta) * t1m;
    const float num   = in_h * (delta * theta * theta + d0 * t1m);
    float y  = in_ch + num / denom;
    float ld = 2.0f * logf(delta)
             + logf(d1 * theta * theta + 2.0f * delta * t1m + d0 * (1.0f - theta) * (1.0f - theta))
             - 2.0f * logf(denom);

    const bool inside = fabsf(xi) <= TAIL;
    y_out[(size_t)b * N_IN + i] = inside ? y : xi;
    float ldv = inside ? ld : 0.0f;

    __shared__ float warp_sums[4];
#pragma unroll
    for (int off = 16; off > 0; off >>= 1)
        ldv += __shfl_down_sync(0xFFFFFFFFu, ldv, off);
    if ((i & 31) == 0) warp_sums[i >> 5] = ldv;
    __syncthreads();
    if (i == 0)
        ld_out[b] = warp_sums[0] + warp_sums[1] + warp_sums[2] + warp_sums[3];
}

// ---------------- launch ----------------
extern "C" void kernel_launch(void* const* d_in, const int* in_sizes, int n_in,
                              void* d_out, int out_size) {
    const float* x      = (const float*)d_in[0];
    const float* context= (const float*)d_in[1];
    const float* ctx_w  = (const float*)d_in[2];
    const float* w0     = (const float*)d_in[3];
    const float* b0     = (const float*)d_in[4];
    const float* w1     = (const float*)d_in[5];
    const float* b1     = (const float*)d_in[6];
    const float* w2     = (const float*)d_in[7];
    const float* b2     = (const float*)d_in[8];
    // masks d_in[9..11] recomputed analytically.

    __nv_bfloat16 *xch, *xcl, *wch, *wcl, *w1h, *w1l, *w2h, *w2l, *h0h, *h0l, *h1h, *h1l;
    float* obuf;
    cudaGetSymbolAddress((void**)&xch, g_xcat_hi); cudaGetSymbolAddress((void**)&xcl, g_xcat_lo);
    cudaGetSymbolAddress((void**)&wch, g_wcat_hi); cudaGetSymbolAddress((void**)&wcl, g_wcat_lo);
    cudaGetSymbolAddress((void**)&w1h, g_w1_hi);   cudaGetSymbolAddress((void**)&w1l, g_w1_lo);
    cudaGetSymbolAddress((void**)&w2h, g_w2_hi);   cudaGetSymbolAddress((void**)&w2l, g_w2_lo);
    cudaGetSymbolAddress((void**)&h0h, g_h0_hi);   cudaGetSymbolAddress((void**)&h0l, g_h0_lo);
    cudaGetSymbolAddress((void**)&h1h, g_h1_hi);   cudaGetSymbolAddress((void**)&h1l, g_h1_lo);
    cudaGetSymbolAddress((void**)&obuf, g_out);

    cudaFuncSetAttribute(gemm_mma, cudaFuncAttributeMaxDynamicSharedMemorySize, GSMEM);

    const int TPB = 256;
    k_prep_xcat<<<(BATCH * KCAT + TPB - 1) / TPB, TPB>>>(x, context, xch, xcl);
    k_prep_wcat<<<(HDIM * KCAT + TPB - 1) / TPB, TPB>>>(ctx_w, w0, wch, wcl);
    k_prep_w1 <<<(HDIM * HDIM + TPB - 1) / TPB, TPB>>>(w1, w1h, w1l);
    k_prep_w2 <<<(N_OUT_P * HDIM + TPB - 1) / TPB, TPB>>>(w2, w2h, w2l);

    // layer 1: [B,256]@[1024,256]^T -> h0 (bias+relu, bf16 split out)
    gemm_mma<<<dim3(HDIM / 128, BATCH / 128), 256, GSMEM>>>(
        xch, xcl, wch, wcl, b0, KCAT, HDIM, h0h, h0l, nullptr, HDIM);
    // layer 2: [B,1024]@[1024,1024]^T -> h1 (bias+relu, bf16 split out)
    gemm_mma<<<dim3(HDIM / 128, BATCH / 128), 256, GSMEM>>>(
        h0h, h0l, w1h, w1l, b1, HDIM, HDIM, h1h, h1l, nullptr, HDIM);
    // layer 3: [B,1024]@[3072,1024]^T -> out (bias, fp32 out, padded N)
    gemm_mma<<<dim3(N_OUT_P / 128, BATCH / 128), 256, GSMEM>>>(
        h1h, h1l, w2h, w2l, b2, HDIM, N_OUT, nullptr, nullptr, obuf, N_OUT_P);

    float* yout = (float*)d_out;
    float* ldout = (float*)d_out + (size_t)BATCH * N_IN;
    k_spline<<<BATCH, N_IN>>>(x, obuf, yout, ldout);
}

// round 4
// speedup vs baseline: 4.5431x; 1.4851x over previous
#include <cuda_runtime.h>
#include <cuda_bf16.h>
#include <math.h>
#include <stdint.h>

// ---------------- problem constants ----------------
#define BATCH   16384
#define N_IN    128
#define CTX     128
#define HDIM    1024
#define NB      8
#define OUT_MULT 23                  // 3*NB - 1
#define N_OUT   (N_IN * OUT_MULT)    // 2944
#define N_OUT_P 3072                 // padded
#define KCAT    (CTX + N_IN)         // 256
#define TAIL    3.0f
#define MIN_W   0.001f
#define MIN_H   0.001f
#define MIN_D   0.001f
#define RQS_SCALE 724.07734393502f   // sqrt(1024*1024/2)

// ---------------- scratch ----------------
__device__ __nv_bfloat16 g_xcat_hi[(size_t)BATCH * KCAT];
__device__ __nv_bfloat16 g_xcat_lo[(size_t)BATCH * KCAT];
__device__ __nv_bfloat16 g_wcat_hi[(size_t)HDIM * KCAT];
__device__ __nv_bfloat16 g_wcat_lo[(size_t)HDIM * KCAT];
__device__ __nv_bfloat16 g_w1_hi[(size_t)HDIM * HDIM];
__device__ __nv_bfloat16 g_w1_lo[(size_t)HDIM * HDIM];
__device__ __nv_bfloat16 g_w2_hi[(size_t)N_OUT_P * HDIM];
__device__ __nv_bfloat16 g_w2_lo[(size_t)N_OUT_P * HDIM];
__device__ __nv_bfloat16 g_h0_hi[(size_t)BATCH * HDIM];
__device__ __nv_bfloat16 g_h0_lo[(size_t)BATCH * HDIM];
__device__ __nv_bfloat16 g_h1_hi[(size_t)BATCH * HDIM];
__device__ __nv_bfloat16 g_h1_lo[(size_t)BATCH * HDIM];
__device__ float         g_out[(size_t)BATCH * N_OUT_P];
__device__ float         g_b0p[HDIM];
__device__ float         g_b1p[HDIM];

// ---------------- degree-sorted hidden permutation (analytic) ----------------
// residue r = h % 127. Counts: r<8 -> 9 copies, r>=8 -> 8 copies (HDIM=1024).
// sorted index j -> (r, copy c); orig h = c*127 + r.
// start(r) = first sorted index with residue r = 8r + min(r,8).
__host__ __device__ __forceinline__ int sorted_res(int j) {
    return (j < 72) ? (j / 9) : (8 + (j - 72) / 8);
}
__host__ __device__ __forceinline__ int sorted_orig(int j) {
    int r, c;
    if (j < 72) { r = j / 9; c = j % 9; }
    else        { int u = j - 72; r = 8 + u / 8; c = u % 8; }
    return c * 127 + r;
}

// ---------------- baseline-PTX helpers (compute_103-safe) ----------------
__device__ __forceinline__ uint32_t smem_to_u32(const void* p) {
    uint32_t a;
    asm("{ .reg .u64 t; cvta.to.shared.u64 t, %1; cvt.u32.u64 %0, t; }" : "=r"(a) : "l"(p));
    return a;
}

#define CP_ASYNC16(saddr, gptr) \
    asm volatile("cp.async.cg.shared.global [%0], [%1], 16;" :: "r"(saddr), "l"(gptr) : "memory")
#define CP_COMMIT()   asm volatile("cp.async.commit_group;" ::: "memory")
#define CP_WAIT(n)    asm volatile("cp.async.wait_group %0;" :: "n"(n) : "memory")

#define LDSM4(R, addr) \
    asm volatile("ldmatrix.sync.aligned.m8n8.x4.shared.b16 {%0,%1,%2,%3}, [%4];" \
        : "=r"((R)[0]), "=r"((R)[1]), "=r"((R)[2]), "=r"((R)[3]) : "r"(addr))
#define LDSM2(R, addr) \
    asm volatile("ldmatrix.sync.aligned.m8n8.x2.shared.b16 {%0,%1}, [%2];" \
        : "=r"((R)[0]), "=r"((R)[1]) : "r"(addr))

#define MMA_BF16(C, A, B) \
    asm volatile("mma.sync.aligned.m16n8k16.row.col.f32.bf16.bf16.f32 " \
        "{%0,%1,%2,%3}, {%4,%5,%6,%7}, {%8,%9}, {%0,%1,%2,%3};" \
        : "+f"((C)[0]), "+f"((C)[1]), "+f"((C)[2]), "+f"((C)[3]) \
        : "r"((A)[0]), "r"((A)[1]), "r"((A)[2]), "r"((A)[3]), "r"((B)[0]), "r"((B)[1]))

// ---------------- prep kernels ----------------
__device__ __forceinline__ void split_bf16(float v, __nv_bfloat16& h, __nv_bfloat16& l) {
    h = __float2bfloat16_rn(v);
    l = __float2bfloat16_rn(v - __bfloat162float(h));
}

__global__ void k_prep_xcat(const float* __restrict__ x, const float* __restrict__ ctx,
                            __nv_bfloat16* __restrict__ hi, __nv_bfloat16* __restrict__ lo) {
    int idx = blockIdx.x * blockDim.x + threadIdx.x;
    if (idx >= BATCH * KCAT) return;
    int b = idx >> 8, c = idx & 255;
    float v = (c < CTX) ? ctx[b * CTX + c] : x[b * N_IN + (c - CTX)];
    split_bf16(v, hi[idx], lo[idx]);
}

// wcat rows in SORTED hidden order; x-half masked by r >= i
__global__ void k_prep_wcat(const float* __restrict__ ctxw, const float* __restrict__ w0,
                            __nv_bfloat16* __restrict__ hi, __nv_bfloat16* __restrict__ lo) {
    int idx = blockIdx.x * blockDim.x + threadIdx.x;
    if (idx >= HDIM * KCAT) return;
    int j = idx >> 8, c = idx & 255;
    int h = sorted_orig(j), r = sorted_res(j);
    float v;
    if (c < CTX) v = ctxw[h * CTX + c];
    else { int i = c - CTX; v = (r >= i) ? w0[h * N_IN + i] : 0.0f; }
    split_bf16(v, hi[idx], lo[idx]);
}

// w1 in sorted order on BOTH dims; mask r_out >= r_in
__global__ void k_prep_w1(const float* __restrict__ w1,
                          __nv_bfloat16* __restrict__ hi, __nv_bfloat16* __restrict__ lo) {
    int idx = blockIdx.x * blockDim.x + threadIdx.x;
    if (idx >= HDIM * HDIM) return;
    int j = idx >> 10, j2 = idx & 1023;
    float v = (sorted_res(j) >= sorted_res(j2))
            ? w1[(size_t)sorted_orig(j) * HDIM + sorted_orig(j2)] : 0.0f;
    split_bf16(v, hi[idx], lo[idx]);
}

// w2: rows natural o (padded), cols sorted; mask (o/23) > r
__global__ void k_prep_w2(const float* __restrict__ w2,
                          __nv_bfloat16* __restrict__ hi, __nv_bfloat16* __restrict__ lo) {
    int idx = blockIdx.x * blockDim.x + threadIdx.x;
    if (idx >= N_OUT_P * HDIM) return;
    int o = idx >> 10, j = idx & 1023;
    float v = 0.0f;
    if (o < N_OUT && ((o / OUT_MULT) > sorted_res(j)))
        v = w2[(size_t)o * HDIM + sorted_orig(j)];
    split_bf16(v, hi[idx], lo[idx]);
}

__global__ void k_prep_bias(const float* __restrict__ b0, const float* __restrict__ b1,
                            float* __restrict__ b0p, float* __restrict__ b1p) {
    int j = blockIdx.x * blockDim.x + threadIdx.x;
    if (j >= HDIM) return;
    int h = sorted_orig(j);
    b0p[j] = b0[h];
    b1p[j] = b1[h];
}

// ---------------- mma.sync split-bf16 GEMM with triangular K-skip ----------
// C[M,N] = A[M,K] @ B[N,K]^T, A=Ahi+Alo, B=Bhi+Blo (drop lo*lo).
// CTA tile 128x128, BK=64, 8 warps (4M x 2N), warp tile 32x64, double buffered.
// mode: 0 = layer1 (K=256: 128 ctx dense + triangular x),
//       1 = layer2 (sorted->sorted triangular),
//       2 = layer3 (natural o rows vs sorted cols),
//       3 = dense (unused)

#define ST_AHI 0
#define ST_ALO 16384
#define ST_BHI 32768
#define ST_BLO 49152
#define STAGE_SZ 65536
#define GSMEM (2 * STAGE_SZ + 1024)

__global__ __launch_bounds__(256, 1)
void gemm_mma(const __nv_bfloat16* __restrict__ Ahi, const __nv_bfloat16* __restrict__ Alo,
              const __nv_bfloat16* __restrict__ Bhi, const __nv_bfloat16* __restrict__ Blo,
              const float* __restrict__ bias, int K, int nvalid, int mode,
              __nv_bfloat16* __restrict__ Chi, __nv_bfloat16* __restrict__ Clo,
              float* __restrict__ Cf, int ldc) {
    extern __shared__ char smem[];
    const uint32_t sb = smem_to_u32(smem);
    float* bias_s = (float*)(smem + 2 * STAGE_SZ);

    const int tid = threadIdx.x;
    const int lane = tid & 31, wid = tid >> 5;
    const int gm = blockIdx.y * 128;
    const int gn = blockIdx.x * 128;

    if (tid < 128) bias_s[tid] = (gn + tid < nvalid) ? bias[gn + tid] : 0.0f;

    // ----- per-CTA effective K from the mask structure -----
    int keff = K;
    if (mode == 0) {
        int r = sorted_res(gn + 127);
        keff = CTX + r + 1;                  // ctx dense + x cols i <= r
    } else if (mode == 1) {
        int rp = sorted_res(gn + 127) + 1;   // need residues <= r_max
        keff = 8 * rp + min(rp, 8);          // start(r_max+1)
    } else if (mode == 2) {
        int q = min(gn + 127, N_OUT - 1) / OUT_MULT;  // rows with r < q
        keff = 8 * q + min(q, 8);            // start(q)
    }
    keff = min(K, (keff + 63) & ~63);        // round up to chunk (masked zeros cover)

    int r_[4], c_[4]; uint32_t soff_[4];
#pragma unroll
    for (int i = 0; i < 4; i++) {
        int u = i * 256 + tid;
        r_[i] = u >> 3; c_[i] = u & 7;
        soff_[i] = (uint32_t)(r_[i] * 128 + ((c_[i] ^ (r_[i] & 7)) << 4));
    }

    const int wm = (wid & 3) * 32;
    const int nb = (wid >> 2) * 64;
    const int lr = lane & 7;
    const int gA = (lane >> 3) & 1;
    const int cpartA = (lane >> 4) & 1;
    const int cpartB = (lane >> 3) & 1;
    const uint32_t xorv = (uint32_t)lr << 4;
    const uint32_t pA = (uint32_t)((wm + gA * 8 + lr) * 128);
    const uint32_t pB = (uint32_t)((nb + lr) * 128);

    float acc[2][8][4];
#pragma unroll
    for (int t = 0; t < 2; t++)
#pragma unroll
        for (int j = 0; j < 8; j++)
#pragma unroll
            for (int q = 0; q < 4; q++) acc[t][j][q] = 0.0f;

    const int nch = keff >> 6;

    auto load_stage = [&](int s, int k0) {
        uint32_t base = sb + (uint32_t)s * STAGE_SZ;
#pragma unroll
        for (int i = 0; i < 4; i++) {
            size_t ga = (size_t)(gm + r_[i]) * K + k0 + c_[i] * 8;
            size_t gb = (size_t)(gn + r_[i]) * K + k0 + c_[i] * 8;
            CP_ASYNC16(base + ST_AHI + soff_[i], Ahi + ga);
            CP_ASYNC16(base + ST_ALO + soff_[i], Alo + ga);
            CP_ASYNC16(base + ST_BHI + soff_[i], Bhi + gb);
            CP_ASYNC16(base + ST_BLO + soff_[i], Blo + gb);
        }
    };

    load_stage(0, 0);
    CP_COMMIT();

    for (int c = 0; c < nch; c++) {
        if (c + 1 < nch) { load_stage((c + 1) & 1, (c + 1) << 6); CP_COMMIT(); }
        if (c + 1 < nch) CP_WAIT(1); else CP_WAIT(0);
        __syncthreads();

        const uint32_t sA = sb + (uint32_t)(c & 1) * STAGE_SZ;
#pragma unroll
        for (int ks = 0; ks < 4; ks++) {
            const uint32_t offA = (uint32_t)(((ks * 2 + cpartA) << 4)) ^ xorv;
            const uint32_t offB = (uint32_t)(((ks * 2 + cpartB) << 4)) ^ xorv;
            uint32_t ah0[4], ah1[4], al0[4], al1[4];
            LDSM4(ah0, sA + ST_AHI + pA + offA);
            LDSM4(ah1, sA + ST_AHI + pA + 2048 + offA);
            LDSM4(al0, sA + ST_ALO + pA + offA);
            LDSM4(al1, sA + ST_ALO + pA + 2048 + offA);
#pragma unroll
            for (int j = 0; j < 8; j++) {
                uint32_t bh[2], bl[2];
                LDSM2(bh, sA + ST_BHI + pB + (uint32_t)(j * 1024) + offB);
                LDSM2(bl, sA + ST_BLO + pB + (uint32_t)(j * 1024) + offB);
                MMA_BF16(acc[0][j], ah0, bh);
                MMA_BF16(acc[1][j], ah1, bh);
                MMA_BF16(acc[0][j], ah0, bl);
                MMA_BF16(acc[1][j], ah1, bl);
                MMA_BF16(acc[0][j], al0, bh);
                MMA_BF16(acc[1][j], al1, bh);
            }
        }
        __syncthreads();
    }

    // ---------------- epilogue ----------------
    const int qrow = lane >> 2;
    const int qcol = 2 * (lane & 3);
#pragma unroll
    for (int t = 0; t < 2; t++) {
#pragma unroll
        for (int j = 0; j < 8; j++) {
            const int colL = nb + j * 8 + qcol;
            const float b0 = bias_s[colL], b1 = bias_s[colL + 1];
#pragma unroll
            for (int h = 0; h < 2; h++) {
                const int row = gm + wm + t * 16 + h * 8 + qrow;
                float v0 = acc[t][j][h * 2 + 0] + b0;
                float v1 = acc[t][j][h * 2 + 1] + b1;
                if (Cf) {
                    float2 f2 = make_float2(v0, v1);
                    *(float2*)(Cf + (size_t)row * ldc + gn + colL) = f2;
                } else {
                    v0 = fmaxf(v0, 0.0f); v1 = fmaxf(v1, 0.0f);
                    __nv_bfloat16 h0 = __float2bfloat16_rn(v0);
                    __nv_bfloat16 h1 = __float2bfloat16_rn(v1);
                    __nv_bfloat16 l0 = __float2bfloat16_rn(v0 - __bfloat162float(h0));
                    __nv_bfloat16 l1 = __float2bfloat16_rn(v1 - __bfloat162float(h1));
                    uint32_t wh = (uint32_t)__bfloat16_as_ushort(h0) | ((uint32_t)__bfloat16_as_ushort(h1) << 16);
                    uint32_t wl = (uint32_t)__bfloat16_as_ushort(l0) | ((uint32_t)__bfloat16_as_ushort(l1) << 16);
                    *(uint32_t*)(Chi + (size_t)row * ldc + gn + colL) = wh;
                    *(uint32_t*)(Clo + (size_t)row * ldc + gn + colL) = wl;
                }
            }
        }
    }
}

// ---------------- RQS spline + logdet reduction ----------------
__device__ __forceinline__ float softplusf(float v) {
    return (v > 20.0f) ? v : log1pf(expf(v));
}

__global__ void k_spline(const float* __restrict__ x, const float* __restrict__ out,
                         float* __restrict__ y_out, float* __restrict__ ld_out) {
    const int b = blockIdx.x;
    const int i = threadIdx.x;

    __shared__ float srow[N_OUT];
    const float4* orow = (const float4*)(out + (size_t)b * N_OUT_P);
#pragma unroll
    for (int u = i; u < N_OUT / 4; u += N_IN) ((float4*)srow)[u] = orow[u];
    __syncthreads();

    const float* o = srow + i * OUT_MULT;
    const float xi = x[(size_t)b * N_IN + i];

    float uw[NB], uh[NB];
#pragma unroll
    for (int j = 0; j < NB; j++) {
        uw[j] = o[j]      * (1.0f / RQS_SCALE);
        uh[j] = o[NB + j] * (1.0f / RQS_SCALE);
    }
    float mw = uw[0], mh = uh[0];
#pragma unroll
    for (int j = 1; j < NB; j++) { mw = fmaxf(mw, uw[j]); mh = fmaxf(mh, uh[j]); }
    float ew[NB], eh[NB], sw = 0.0f, sh = 0.0f;
#pragma unroll
    for (int j = 0; j < NB; j++) {
        ew[j] = expf(uw[j] - mw); sw += ew[j];
        eh[j] = expf(uh[j] - mh); sh += eh[j];
    }
    const float rw = (1.0f - MIN_W * NB) / sw;
    const float rh = (1.0f - MIN_H * NB) / sh;

    float cw[NB + 1], ch[NB + 1];
    cw[0] = -TAIL; ch[0] = -TAIL;
    float accw = 0.0f, acch = 0.0f;
#pragma unroll
    for (int j = 0; j < NB; j++) {
        accw += MIN_W + rw * ew[j];
        acch += MIN_H + rh * eh[j];
        cw[j + 1] = 2.0f * TAIL * accw - TAIL;
        ch[j + 1] = 2.0f * TAIL * acch - TAIL;
    }
    cw[NB] = TAIL; ch[NB] = TAIL;

    float d[NB + 1];
    d[0] = 1.0f; d[NB] = 1.0f;
#pragma unroll
    for (int j = 1; j < NB; j++) d[j] = MIN_D + softplusf(o[2 * NB + j - 1]);

    const float xc = fminf(fmaxf(xi, -TAIL), TAIL);
    int idx = 0;
#pragma unroll
    for (int k = 1; k <= NB; k++) idx += (xc >= cw[k]) ? 1 : 0;
    idx = min(idx, NB - 1);

    const float in_cw = cw[idx];
    const float in_w  = cw[idx + 1] - cw[idx];
    const float in_ch = ch[idx];
    const float in_h  = ch[idx + 1] - ch[idx];
    const float delta = in_h / in_w;
    const float d0 = d[idx], d1 = d[idx + 1];

    const float theta = (xc - in_cw) / in_w;
    const float t1m   = theta * (1.0f - theta);
    const float denom = delta + (d0 + d1 - 2.0f * delta) * t1m;
    const float num   = in_h * (delta * theta * theta + d0 * t1m);
    float y  = in_ch + num / denom;
    float ld = 2.0f * logf(delta)
             + logf(d1 * theta * theta + 2.0f * delta * t1m + d0 * (1.0f - theta) * (1.0f - theta))
             - 2.0f * logf(denom);

    const bool inside = fabsf(xi) <= TAIL;
    y_out[(size_t)b * N_IN + i] = inside ? y : xi;
    float ldv = inside ? ld : 0.0f;

    __shared__ float warp_sums[4];
#pragma unroll
    for (int off = 16; off > 0; off >>= 1)
        ldv += __shfl_down_sync(0xFFFFFFFFu, ldv, off);
    if ((i & 31) == 0) warp_sums[i >> 5] = ldv;
    __syncthreads();
    if (i == 0)
        ld_out[b] = warp_sums[0] + warp_sums[1] + warp_sums[2] + warp_sums[3];
}

// ---------------- launch ----------------
extern "C" void kernel_launch(void* const* d_in, const int* in_sizes, int n_in,
                              void* d_out, int out_size) {
    const float* x      = (const float*)d_in[0];
    const float* context= (const float*)d_in[1];
    const float* ctx_w  = (const float*)d_in[2];
    const float* w0     = (const float*)d_in[3];
    const float* b0     = (const float*)d_in[4];
    const float* w1     = (const float*)d_in[5];
    const float* b1     = (const float*)d_in[6];
    const float* w2     = (const float*)d_in[7];
    const float* b2     = (const float*)d_in[8];

    __nv_bfloat16 *xch, *xcl, *wch, *wcl, *w1h, *w1l, *w2h, *w2l, *h0h, *h0l, *h1h, *h1l;
    float *obuf, *b0p, *b1p;
    cudaGetSymbolAddress((void**)&xch, g_xcat_hi); cudaGetSymbolAddress((void**)&xcl, g_xcat_lo);
    cudaGetSymbolAddress((void**)&wch, g_wcat_hi); cudaGetSymbolAddress((void**)&wcl, g_wcat_lo);
    cudaGetSymbolAddress((void**)&w1h, g_w1_hi);   cudaGetSymbolAddress((void**)&w1l, g_w1_lo);
    cudaGetSymbolAddress((void**)&w2h, g_w2_hi);   cudaGetSymbolAddress((void**)&w2l, g_w2_lo);
    cudaGetSymbolAddress((void**)&h0h, g_h0_hi);   cudaGetSymbolAddress((void**)&h0l, g_h0_lo);
    cudaGetSymbolAddress((void**)&h1h, g_h1_hi);   cudaGetSymbolAddress((void**)&h1l, g_h1_lo);
    cudaGetSymbolAddress((void**)&obuf, g_out);
    cudaGetSymbolAddress((void**)&b0p, g_b0p);
    cudaGetSymbolAddress((void**)&b1p, g_b1p);

    cudaFuncSetAttribute(gemm_mma, cudaFuncAttributeMaxDynamicSharedMemorySize, GSMEM);

    const int TPB = 256;
    k_prep_xcat<<<(BATCH * KCAT + TPB - 1) / TPB, TPB>>>(x, context, xch, xcl);
    k_prep_wcat<<<(HDIM * KCAT + TPB - 1) / TPB, TPB>>>(ctx_w, w0, wch, wcl);
    k_prep_w1 <<<(HDIM * HDIM + TPB - 1) / TPB, TPB>>>(w1, w1h, w1l);
    k_prep_w2 <<<(N_OUT_P * HDIM + TPB - 1) / TPB, TPB>>>(w2, w2h, w2l);
    k_prep_bias<<<(HDIM + TPB - 1) / TPB, TPB>>>(b0, b1, b0p, b1p);

    // layer 1: triangular x-half (mode 0)
    gemm_mma<<<dim3(HDIM / 128, BATCH / 128), 256, GSMEM>>>(
        xch, xcl, wch, wcl, b0p, KCAT, HDIM, 0, h0h, h0l, nullptr, HDIM);
    // layer 2: sorted->sorted triangular (mode 1)
    gemm_mma<<<dim3(HDIM / 128, BATCH / 128), 256, GSMEM>>>(
        h0h, h0l, w1h, w1l, b1p, HDIM, HDIM, 1, h1h, h1l, nullptr, HDIM);
    // layer 3: natural rows vs sorted cols (mode 2)
    gemm_mma<<<dim3(N_OUT_P / 128, BATCH / 128), 256, GSMEM>>>(
        h1h, h1l, w2h, w2l, b2, HDIM, N_OUT, 2, nullptr, nullptr, obuf, N_OUT_P);

    float* yout = (float*)d_out;
    float* ldout = (float*)d_out + (size_t)BATCH * N_IN;
    k_spline<<<BATCH, N_IN>>>(x, obuf, yout, ldout);
}

// round 6
// speedup vs baseline: 4.7628x; 1.0483x over previous
#include <cuda_runtime.h>
#include <cuda_bf16.h>
#include <math.h>
#include <stdint.h>

// ---------------- problem constants ----------------
#define BATCH   16384
#define N_IN    128
#define CTX     128
#define HDIM    1024
#define NB      8
#define OUT_MULT 23                  // 3*NB - 1
#define N_OUT   (N_IN * OUT_MULT)    // 2944 = 23 * 128 exactly
#define N_OUT_P 3072                 // obuf row padding (float4-friendly)
#define KCAT    (CTX + N_IN)         // 256
#define TAIL    3.0f
#define MIN_W   0.001f
#define MIN_H   0.001f
#define MIN_D   0.001f
#define RQS_SCALE 724.07734393502f   // sqrt(1024*1024/2)

// ---------------- scratch ----------------
__device__ __nv_bfloat16 g_xcat_hi[(size_t)BATCH * KCAT];
__device__ __nv_bfloat16 g_xcat_lo[(size_t)BATCH * KCAT];
__device__ __nv_bfloat16 g_wcat_hi[(size_t)HDIM * KCAT];
__device__ __nv_bfloat16 g_wcat_lo[(size_t)HDIM * KCAT];
__device__ __nv_bfloat16 g_w1_hi[(size_t)HDIM * HDIM];
__device__ __nv_bfloat16 g_w1_lo[(size_t)HDIM * HDIM];
__device__ __nv_bfloat16 g_w2_hi[(size_t)N_OUT * HDIM];
__device__ __nv_bfloat16 g_w2_lo[(size_t)N_OUT * HDIM];
__device__ __nv_bfloat16 g_h0_hi[(size_t)BATCH * HDIM];
__device__ __nv_bfloat16 g_h0_lo[(size_t)BATCH * HDIM];
__device__ __nv_bfloat16 g_h1_hi[(size_t)BATCH * HDIM];
__device__ __nv_bfloat16 g_h1_lo[(size_t)BATCH * HDIM];
__device__ float         g_out[(size_t)BATCH * N_OUT_P];
__device__ float         g_b0p[HDIM];
__device__ float         g_b1p[HDIM];

// ---------------- degree-sorted hidden permutation (analytic) ----------------
__host__ __device__ __forceinline__ int sorted_res(int j) {
    return (j < 72) ? (j / 9) : (8 + (j - 72) / 8);
}
__host__ __device__ __forceinline__ int sorted_orig(int j) {
    int r, c;
    if (j < 72) { r = j / 9; c = j % 9; }
    else        { int u = j - 72; r = 8 + u / 8; c = u % 8; }
    return c * 127 + r;
}

// ---------------- baseline-PTX helpers (compute_103-safe) ----------------
__device__ __forceinline__ uint32_t smem_to_u32(const void* p) {
    uint32_t a;
    asm("{ .reg .u64 t; cvta.to.shared.u64 t, %1; cvt.u32.u64 %0, t; }" : "=r"(a) : "l"(p));
    return a;
}

#define CP_ASYNC16(saddr, gptr) \
    asm volatile("cp.async.cg.shared.global [%0], [%1], 16;" :: "r"(saddr), "l"(gptr) : "memory")
#define CP_COMMIT()   asm volatile("cp.async.commit_group;" ::: "memory")
#define CP_WAIT(n)    asm volatile("cp.async.wait_group %0;" :: "n"(n) : "memory")

#define LDSM4(R, addr) \
    asm volatile("ldmatrix.sync.aligned.m8n8.x4.shared.b16 {%0,%1,%2,%3}, [%4];" \
        : "=r"((R)[0]), "=r"((R)[1]), "=r"((R)[2]), "=r"((R)[3]) : "r"(addr))

#define MMA_BF16(C, A, B0, B1) \
    asm volatile("mma.sync.aligned.m16n8k16.row.col.f32.bf16.bf16.f32 " \
        "{%0,%1,%2,%3}, {%4,%5,%6,%7}, {%8,%9}, {%0,%1,%2,%3};" \
        : "+f"((C)[0]), "+f"((C)[1]), "+f"((C)[2]), "+f"((C)[3]) \
        : "r"((A)[0]), "r"((A)[1]), "r"((A)[2]), "r"((A)[3]), "r"(B0), "r"(B1))

// ---------------- prep kernels ----------------
__device__ __forceinline__ void split_bf16(float v, __nv_bfloat16& h, __nv_bfloat16& l) {
    h = __float2bfloat16_rn(v);
    l = __float2bfloat16_rn(v - __bfloat162float(h));
}

__global__ void k_prep_xcat(const float* __restrict__ x, const float* __restrict__ ctx,
                            __nv_bfloat16* __restrict__ hi, __nv_bfloat16* __restrict__ lo) {
    int idx = blockIdx.x * blockDim.x + threadIdx.x;
    if (idx >= BATCH * KCAT) return;
    int b = idx >> 8, c = idx & 255;
    float v = (c < CTX) ? ctx[b * CTX + c] : x[b * N_IN + (c - CTX)];
    split_bf16(v, hi[idx], lo[idx]);
}

__global__ void k_prep_wcat(const float* __restrict__ ctxw, const float* __restrict__ w0,
                            __nv_bfloat16* __restrict__ hi, __nv_bfloat16* __restrict__ lo) {
    int idx = blockIdx.x * blockDim.x + threadIdx.x;
    if (idx >= HDIM * KCAT) return;
    int j = idx >> 8, c = idx & 255;
    int h = sorted_orig(j), r = sorted_res(j);
    float v;
    if (c < CTX) v = ctxw[h * CTX + c];
    else { int i = c - CTX; v = (r >= i) ? w0[h * N_IN + i] : 0.0f; }
    split_bf16(v, hi[idx], lo[idx]);
}

__global__ void k_prep_w1(const float* __restrict__ w1,
                          __nv_bfloat16* __restrict__ hi, __nv_bfloat16* __restrict__ lo) {
    int idx = blockIdx.x * blockDim.x + threadIdx.x;
    if (idx >= HDIM * HDIM) return;
    int j = idx >> 10, j2 = idx & 1023;
    float v = (sorted_res(j) >= sorted_res(j2))
            ? w1[(size_t)sorted_orig(j) * HDIM + sorted_orig(j2)] : 0.0f;
    split_bf16(v, hi[idx], lo[idx]);
}

__global__ void k_prep_w2(const float* __restrict__ w2,
                          __nv_bfloat16* __restrict__ hi, __nv_bfloat16* __restrict__ lo) {
    int idx = blockIdx.x * blockDim.x + threadIdx.x;
    if (idx >= N_OUT * HDIM) return;
    int o = idx >> 10, j = idx & 1023;
    float v = ((o / OUT_MULT) > sorted_res(j)) ? w2[(size_t)o * HDIM + sorted_orig(j)] : 0.0f;
    split_bf16(v, hi[idx], lo[idx]);
}

__global__ void k_prep_bias(const float* __restrict__ b0, const float* __restrict__ b1,
                            float* __restrict__ b0p, float* __restrict__ b1p) {
    int j = blockIdx.x * blockDim.x + threadIdx.x;
    if (j >= HDIM) return;
    int h = sorted_orig(j);
    b0p[j] = b0[h];
    b1p[j] = b1[h];
}

// ---------------- mma.sync split-bf16 GEMM, triangular K-skip, 3-stage -----
#define ST_AHI 0
#define ST_ALO 16384
#define ST_BHI 32768
#define ST_BLO 49152
#define STAGE_SZ 65536
#define NSTAGE 3
#define GSMEM (NSTAGE * STAGE_SZ + 1024)

__global__ __launch_bounds__(256, 1)
void gemm_mma(const __nv_bfloat16* __restrict__ Ahi, const __nv_bfloat16* __restrict__ Alo,
              const __nv_bfloat16* __restrict__ Bhi, const __nv_bfloat16* __restrict__ Blo,
              const float* __restrict__ bias, int K, int nvalid, int mode,
              __nv_bfloat16* __restrict__ Chi, __nv_bfloat16* __restrict__ Clo,
              float* __restrict__ Cf, int ldc) {
    extern __shared__ char smem[];
    const uint32_t sb = smem_to_u32(smem);
    float* bias_s = (float*)(smem + NSTAGE * STAGE_SZ);

    const int tid = threadIdx.x;
    const int lane = tid & 31, wid = tid >> 5;
    const int gm = blockIdx.y * 128;
    const int gn = blockIdx.x * 128;

    if (tid < 128) bias_s[tid] = (gn + tid < nvalid) ? bias[gn + tid] : 0.0f;

    // per-CTA effective K from the mask structure
    int keff = K;
    if (mode == 0) {
        int r = sorted_res(gn + 127);
        keff = CTX + r + 1;
    } else if (mode == 1) {
        int rp = sorted_res(gn + 127) + 1;
        keff = 8 * rp + min(rp, 8);
    } else if (mode == 2) {
        int q = min(gn + 127, N_OUT - 1) / OUT_MULT;
        keff = 8 * q + min(q, 8);
    }
    keff = min(K, (keff + 63) & ~63);

    int r_[4], c_[4]; uint32_t soff_[4];
#pragma unroll
    for (int i = 0; i < 4; i++) {
        int u = i * 256 + tid;
        r_[i] = u >> 3; c_[i] = u & 7;
        soff_[i] = (uint32_t)(r_[i] * 128 + ((c_[i] ^ (r_[i] & 7)) << 4));
    }

    const int wm = (wid & 3) * 32;
    const int nb = (wid >> 2) * 64;
    const int lr = lane & 7;
    const int gA = (lane >> 3) & 1;
    const int cpartA = (lane >> 4) & 1;
    const uint32_t xorv = (uint32_t)lr << 4;
    const uint32_t pA  = (uint32_t)((wm + gA * 8 + lr) * 128);
    // B ldmatrix.x4 pair addressing: group m = lane>>3:
    //   m&1 -> k-half, m>>1 -> j within pair. Row = nb + (m>>1)*8 + lr.
    const int kpB = (lane >> 3) & 1;
    const uint32_t pB4 = (uint32_t)((nb + ((lane >> 4) & 1) * 8 + lr) * 128);

    float acc[2][8][4];
#pragma unroll
    for (int t = 0; t < 2; t++)
#pragma unroll
        for (int j = 0; j < 8; j++)
#pragma unroll
            for (int q = 0; q < 4; q++) acc[t][j][q] = 0.0f;

    const int nch = keff >> 6;

    auto load_stage = [&](int s, int k0) {
        uint32_t base = sb + (uint32_t)s * STAGE_SZ;
#pragma unroll
        for (int i = 0; i < 4; i++) {
            size_t ga = (size_t)(gm + r_[i]) * K + k0 + c_[i] * 8;
            size_t gb = (size_t)(gn + r_[i]) * K + k0 + c_[i] * 8;
            CP_ASYNC16(base + ST_AHI + soff_[i], Ahi + ga);
            CP_ASYNC16(base + ST_ALO + soff_[i], Alo + ga);
            CP_ASYNC16(base + ST_BHI + soff_[i], Bhi + gb);
            CP_ASYNC16(base + ST_BLO + soff_[i], Blo + gb);
        }
    };

    // prologue: 2 stages in flight
    load_stage(0, 0);
    CP_COMMIT();
    if (nch > 1) { load_stage(1, 64); CP_COMMIT(); }

    for (int c = 0; c < nch; c++) {
        // commit ledger at this point: stages 0..min(c+1, nch-1) committed.
        // Need stage c landed -> at most ONE pending group (stage c+1).
        if (c + 1 < nch) CP_WAIT(1); else CP_WAIT(0);
        __syncthreads();   // also: all threads finished reading slot (c-1)%3

        // issue stage c+2 into slot (c+2)%3 == (c-1)%3 — safe after the sync,
        // and it overlaps this chunk's MMA work.
        if (c + 2 < nch) { load_stage((c + 2) % NSTAGE, (c + 2) << 6); CP_COMMIT(); }

        const uint32_t sA = sb + (uint32_t)(c % NSTAGE) * STAGE_SZ;
#pragma unroll
        for (int ks = 0; ks < 4; ks++) {
            const uint32_t offA = (uint32_t)(((ks * 2 + cpartA) << 4)) ^ xorv;
            const uint32_t offB = (uint32_t)(((ks * 2 + kpB) << 4)) ^ xorv;
            uint32_t ah0[4], ah1[4], al0[4], al1[4];
            LDSM4(ah0, sA + ST_AHI + pA + offA);
            LDSM4(ah1, sA + ST_AHI + pA + 2048 + offA);
            LDSM4(al0, sA + ST_ALO + pA + offA);
            LDSM4(al1, sA + ST_ALO + pA + 2048 + offA);
#pragma unroll
            for (int jp = 0; jp < 4; jp++) {
                uint32_t bh4[4], bl4[4];
                const uint32_t baddr = sA + ST_BHI + pB4 + (uint32_t)(jp * 2048) + offB;
                LDSM4(bh4, baddr);
                LDSM4(bl4, baddr + (ST_BLO - ST_BHI));
                const int j0 = jp * 2, j1 = jp * 2 + 1;
                MMA_BF16(acc[0][j0], ah0, bh4[0], bh4[1]);
                MMA_BF16(acc[1][j0], ah1, bh4[0], bh4[1]);
                MMA_BF16(acc[0][j1], ah0, bh4[2], bh4[3]);
                MMA_BF16(acc[1][j1], ah1, bh4[2], bh4[3]);
                MMA_BF16(acc[0][j0], ah0, bl4[0], bl4[1]);
                MMA_BF16(acc[1][j0], ah1, bl4[0], bl4[1]);
                MMA_BF16(acc[0][j1], ah0, bl4[2], bl4[3]);
                MMA_BF16(acc[1][j1], ah1, bl4[2], bl4[3]);
                MMA_BF16(acc[0][j0], al0, bh4[0], bh4[1]);
                MMA_BF16(acc[1][j0], al1, bh4[0], bh4[1]);
                MMA_BF16(acc[0][j1], al0, bh4[2], bh4[3]);
                MMA_BF16(acc[1][j1], al1, bh4[2], bh4[3]);
            }
        }
    }

    // ---------------- epilogue ----------------
    const int qrow = lane >> 2;
    const int qcol = 2 * (lane & 3);
#pragma unroll
    for (int t = 0; t < 2; t++) {
#pragma unroll
        for (int j = 0; j < 8; j++) {
            const int colL = nb + j * 8 + qcol;
            const float b0 = bias_s[colL], b1 = bias_s[colL + 1];
#pragma unroll
            for (int h = 0; h < 2; h++) {
                const int row = gm + wm + t * 16 + h * 8 + qrow;
                float v0 = acc[t][j][h * 2 + 0] + b0;
                float v1 = acc[t][j][h * 2 + 1] + b1;
                if (Cf) {
                    float2 f2 = make_float2(v0, v1);
                    *(float2*)(Cf + (size_t)row * ldc + gn + colL) = f2;
                } else {
                    v0 = fmaxf(v0, 0.0f); v1 = fmaxf(v1, 0.0f);
                    __nv_bfloat16 h0 = __float2bfloat16_rn(v0);
                    __nv_bfloat16 h1 = __float2bfloat16_rn(v1);
                    __nv_bfloat16 l0 = __float2bfloat16_rn(v0 - __bfloat162float(h0));
                    __nv_bfloat16 l1 = __float2bfloat16_rn(v1 - __bfloat162float(h1));
                    uint32_t wh = (uint32_t)__bfloat16_as_ushort(h0) | ((uint32_t)__bfloat16_as_ushort(h1) << 16);
                    uint32_t wl = (uint32_t)__bfloat16_as_ushort(l0) | ((uint32_t)__bfloat16_as_ushort(l1) << 16);
                    *(uint32_t*)(Chi + (size_t)row * ldc + gn + colL) = wh;
                    *(uint32_t*)(Clo + (size_t)row * ldc + gn + colL) = wl;
                }
            }
        }
    }
}

// ---------------- RQS spline + logdet reduction ----------------
__device__ __forceinline__ float softplusf(float v) {
    return (v > 20.0f) ? v : log1pf(expf(v));
}

__global__ void k_spline(const float* __restrict__ x, const float* __restrict__ out,
                         float* __restrict__ y_out, float* __restrict__ ld_out) {
    const int b = blockIdx.x;
    const int i = threadIdx.x;

    __shared__ float srow[N_OUT];
    const float4* orow = (const float4*)(out + (size_t)b * N_OUT_P);
#pragma unroll
    for (int u = i; u < N_OUT / 4; u += N_IN) ((float4*)srow)[u] = orow[u];
    __syncthreads();

    const float* o = srow + i * OUT_MULT;
    const float xi = x[(size_t)b * N_IN + i];

    float uw[NB], uh[NB];
#pragma unroll
    for (int j = 0; j < NB; j++) {
        uw[j] = o[j]      * (1.0f / RQS_SCALE);
        uh[j] = o[NB + j] * (1.0f / RQS_SCALE);
    }
    float mw = uw[0], mh = uh[0];
#pragma unroll
    for (int j = 1; j < NB; j++) { mw = fmaxf(mw, uw[j]); mh = fmaxf(mh, uh[j]); }
    float ew[NB], eh[NB], sw = 0.0f, sh = 0.0f;
#pragma unroll
    for (int j = 0; j < NB; j++) {
        ew[j] = expf(uw[j] - mw); sw += ew[j];
        eh[j] = expf(uh[j] - mh); sh += eh[j];
    }
    const float rw = (1.0f - MIN_W * NB) / sw;
    const float rh = (1.0f - MIN_H * NB) / sh;

    float cw[NB + 1], ch[NB + 1];
    cw[0] = -TAIL; ch[0] = -TAIL;
    float accw = 0.0f, acch = 0.0f;
#pragma unroll
    for (int j = 0; j < NB; j++) {
        accw += MIN_W + rw * ew[j];
        acch += MIN_H + rh * eh[j];
        cw[j + 1] = 2.0f * TAIL * accw - TAIL;
        ch[j + 1] = 2.0f * TAIL * acch - TAIL;
    }
    cw[NB] = TAIL; ch[NB] = TAIL;

    float d[NB + 1];
    d[0] = 1.0f; d[NB] = 1.0f;
#pragma unroll
    for (int j = 1; j < NB; j++) d[j] = MIN_D + softplusf(o[2 * NB + j - 1]);

    const float xc = fminf(fmaxf(xi, -TAIL), TAIL);
    int idx = 0;
#pragma unroll
    for (int k = 1; k <= NB; k++) idx += (xc >= cw[k]) ? 1 : 0;
    idx = min(idx, NB - 1);

    const float in_cw = cw[idx];
    const float in_w  = cw[idx + 1] - cw[idx];
    const float in_ch = ch[idx];
    const float in_h  = ch[idx + 1] - ch[idx];
    const float delta = in_h / in_w;
    const float d0 = d[idx], d1 = d[idx + 1];

    const float theta = (xc - in_cw) / in_w;
    const float t1m   = theta * (1.0f - theta);
    const float denom = delta + (d0 + d1 - 2.0f * delta) * t1m;
    const float num   = in_h * (delta * theta * theta + d0 * t1m);
    float y  = in_ch + num / denom;
    float ld = 2.0f * logf(delta)
             + logf(d1 * theta * theta + 2.0f * delta * t1m + d0 * (1.0f - theta) * (1.0f - theta))
             - 2.0f * logf(denom);

    const bool inside = fabsf(xi) <= TAIL;
    y_out[(size_t)b * N_IN + i] = inside ? y : xi;
    float ldv = inside ? ld : 0.0f;

    __shared__ float warp_sums[4];
#pragma unroll
    for (int off = 16; off > 0; off >>= 1)
        ldv += __shfl_down_sync(0xFFFFFFFFu, ldv, off);
    if ((i & 31) == 0) warp_sums[i >> 5] = ldv;
    __syncthreads();
    if (i == 0)
        ld_out[b] = warp_sums[0] + warp_sums[1] + warp_sums[2] + warp_sums[3];
}

// ---------------- launch ----------------
extern "C" void kernel_launch(void* const* d_in, const int* in_sizes, int n_in,
                              void* d_out, int out_size) {
    const float* x      = (const float*)d_in[0];
    const float* context= (const float*)d_in[1];
    const float* ctx_w  = (const float*)d_in[2];
    const float* w0     = (const float*)d_in[3];
    const float* b0     = (const float*)d_in[4];
    const float* w1     = (const float*)d_in[5];
    const float* b1     = (const float*)d_in[6];
    const float* w2     = (const float*)d_in[7];
    const float* b2     = (const float*)d_in[8];

    __nv_bfloat16 *xch, *xcl, *wch, *wcl, *w1h, *w1l, *w2h, *w2l, *h0h, *h0l, *h1h, *h1l;
    float *obuf, *b0p, *b1p;
    cudaGetSymbolAddress((void**)&xch, g_xcat_hi); cudaGetSymbolAddress((void**)&xcl, g_xcat_lo);
    cudaGetSymbolAddress((void**)&wch, g_wcat_hi); cudaGetSymbolAddress((void**)&wcl, g_wcat_lo);
    cudaGetSymbolAddress((void**)&w1h, g_w1_hi);   cudaGetSymbolAddress((void**)&w1l, g_w1_lo);
    cudaGetSymbolAddress((void**)&w2h, g_w2_hi);   cudaGetSymbolAddress((void**)&w2l, g_w2_lo);
    cudaGetSymbolAddress((void**)&h0h, g_h0_hi);   cudaGetSymbolAddress((void**)&h0l, g_h0_lo);
    cudaGetSymbolAddress((void**)&h1h, g_h1_hi);   cudaGetSymbolAddress((void**)&h1l, g_h1_lo);
    cudaGetSymbolAddress((void**)&obuf, g_out);
    cudaGetSymbolAddress((void**)&b0p, g_b0p);
    cudaGetSymbolAddress((void**)&b1p, g_b1p);

    cudaFuncSetAttribute(gemm_mma, cudaFuncAttributeMaxDynamicSharedMemorySize, GSMEM);

    const int TPB = 256;
    k_prep_xcat<<<(BATCH * KCAT + TPB - 1) / TPB, TPB>>>(x, context, xch, xcl);
    k_prep_wcat<<<(HDIM * KCAT + TPB - 1) / TPB, TPB>>>(ctx_w, w0, wch, wcl);
    k_prep_w1 <<<(HDIM * HDIM + TPB - 1) / TPB, TPB>>>(w1, w1h, w1l);
    k_prep_w2 <<<(N_OUT * HDIM + TPB - 1) / TPB, TPB>>>(w2, w2h, w2l);
    k_prep_bias<<<(HDIM + TPB - 1) / TPB, TPB>>>(b0, b1, b0p, b1p);

    // layer 1: triangular x-half (mode 0)
    gemm_mma<<<dim3(HDIM / 128, BATCH / 128), 256, GSMEM>>>(
        xch, xcl, wch, wcl, b0p, KCAT, HDIM, 0, h0h, h0l, nullptr, HDIM);
    // layer 2: sorted->sorted triangular (mode 1)
    gemm_mma<<<dim3(HDIM / 128, BATCH / 128), 256, GSMEM>>>(
        h0h, h0l, w1h, w1l, b1p, HDIM, HDIM, 1, h1h, h1l, nullptr, HDIM);
    // layer 3: natural rows vs sorted cols (mode 2); 2944 = 23 exact N-tiles
    gemm_mma<<<dim3(N_OUT / 128, BATCH / 128), 256, GSMEM>>>(
        h1h, h1l, w2h, w2l, b2, HDIM, N_OUT, 2, nullptr, nullptr, obuf, N_OUT_P);

    float* yout = (float*)d_out;
    float* ldout = (float*)d_out + (size_t)BATCH * N_IN;
    k_spline<<<BATCH, N_IN>>>(x, obuf, yout, ldout);
}